// round 15
// baseline (speedup 1.0000x reference)
#include <cuda_runtime.h>
#include <cuda_bf16.h>

// x: [32, 512, 512, 3] f32  -> out: [32, 128, 128, 3] f32
// 13-tap separable gaussian (sigma=1.5), zero padding, out = blur[4i, 4j]
//
// DYNAMIC WORK-STEALING over 1024 self-contained 4-row groups:
// 296 resident CTAs (2/SM) pull group ids from a global atomic counter
// (prefetched one iteration ahead, parity-double-buffered in smem), so
// per-SM load balances itself (no static-split makespan loss, no tail).
// Per group: vertical scatter-accumulate stream (PF=6 ring, __ldcs/__ldg
// cache segregation), planar smem, horizontal pass instruction-interleaved
// into the next group's vertical loop. __stcs outputs.

#define ROWF4   384              // float4 per input image row (512*3/4)
#define PROW    528              // floats per padded plane row (8 + 512 + 8)
#define GROWS   4                // output rows per group
#define NGRP    1024             // 32 images x 32 groups
#define GPLANE  (GROWS * PROW)   // floats per plane per group    = 2112
#define GBUF    (3 * GPLANE)     // floats per group buffer       = 6336
#define SMEM_BYTES (2 * GBUF * 4 + 16)   // ping-pong + group-id slots

#define GNIN    (4 * GROWS + 9)  // input rows per group          = 25
#define PF      6                // ring depth; PF>=6 -> R0+s+PF >= 0 always

#define NCTA    296              // 2 CTAs/SM x 148 SMs

__device__ int g_counter;        // reset to 0 by kernel_launch each call

__device__ __forceinline__ float4 f4zero() { return make_float4(0.f, 0.f, 0.f, 0.f); }

// one horizontal output row rr from a group buffer
__device__ __forceinline__ void phase2_row(
    const float* __restrict__ smbuf, int rr, int j, int c,
    float* __restrict__ opix, const float* __restrict__ Wt)
{
    const float4* sp4 = reinterpret_cast<const float4*>(smbuf)
                      + c * (GPLANE / 4) + rr * (PROW / 4) + j;
    float4 a = sp4[0];
    float4 b = sp4[1];
    float4 d = sp4[2];
    float4 e = sp4[3];
    // s[0..15] = cols 4j-8 .. 4j+7 ; taps at s[2..14]
    float acch;
    acch = Wt[0] * a.z;
    acch = fmaf(Wt[1],  a.w, acch);
    acch = fmaf(Wt[2],  b.x, acch);
    acch = fmaf(Wt[3],  b.y, acch);
    acch = fmaf(Wt[4],  b.z, acch);
    acch = fmaf(Wt[5],  b.w, acch);
    acch = fmaf(Wt[6],  d.x, acch);
    acch = fmaf(Wt[7],  d.y, acch);
    acch = fmaf(Wt[8],  d.z, acch);
    acch = fmaf(Wt[9],  d.w, acch);
    acch = fmaf(Wt[10], e.x, acch);
    acch = fmaf(Wt[11], e.y, acch);
    acch = fmaf(Wt[12], e.z, acch);
    __stcs(&opix[rr * 384], acch);           // streaming store (never re-read)
}

// vertical streaming pass for one 4-row group; if P2BUF != nullptr, one
// phase-2 row of the OTHER buffer is interleaved at s = 5, 11, 17, 23.
__device__ __forceinline__ void phase1_group(
    const float4* __restrict__ xcol, int R0,
    float* __restrict__ smbuf, const int* __restrict__ sbase,
    const float* __restrict__ Wt,
    const float* __restrict__ P2BUF, int j, int c, float* __restrict__ p2opix)
{
    float4 buf[PF];
    #pragma unroll
    for (int s = 0; s < PF; ++s) {               // preload rows R0 .. R0+5
        int r = R0 + s;                          // boundary rows: allocate in L2
        buf[s] = (r >= 0) ? __ldg(xcol + r * ROWF4) : f4zero();
    }

    float4 acc[GROWS];
    #pragma unroll
    for (int q = 0; q < GROWS; ++q) acc[q] = f4zero();

    #pragma unroll
    for (int s = 0; s < GNIN; ++s) {
        const float4 v = buf[s % PF];

        if (s + PF < GNIN) {                     // refill; R0+s+PF >= 0 (PF>=6)
            const int sr = s + PF;               // row index within group: 6..24
            int r = R0 + sr;
            if (r < 512) {
                if (sr >= GNIN - 9) {
                    buf[s % PF] = __ldg(xcol + r * ROWF4);   // re-read: allocate
                } else {
                    buf[s % PF] = __ldcs(xcol + r * ROWF4);  // read-once: evict-first
                }
            } else {
                buf[s % PF] = f4zero();
            }
        }

        const int p = s & 3;
        #pragma unroll
        for (int k = p; k <= 12; k += 4) {       // taps congruent to s mod 4
            const int ii = (s - k) >> 2;
            if (ii >= 0 && ii < GROWS) {
                const float wk = Wt[k];
                acc[ii].x = fmaf(wk, v.x, acc[ii].x);
                acc[ii].y = fmaf(wk, v.y, acc[ii].y);
                acc[ii].z = fmaf(wk, v.z, acc[ii].z);
                acc[ii].w = fmaf(wk, v.w, acc[ii].w);
            }
        }

        // output row ii completes at s = 4*ii + 12 -> flush (4x STS.32)
        if (s >= 12 && ((s - 12) & 3) == 0) {
            const int ii = (s - 12) >> 2;
            const int ro = ii * PROW;
            smbuf[sbase[0] + ro] = acc[ii].x;
            smbuf[sbase[1] + ro] = acc[ii].y;
            smbuf[sbase[2] + ro] = acc[ii].z;
            smbuf[sbase[3] + ro] = acc[ii].w;
        }

        // interleaved horizontal row of the previous group's buffer
        if (P2BUF != nullptr && (s == 5 || s == 11 || s == 17 || s == 23)) {
            phase2_row(P2BUF, (s - 5) / 6, j, c, p2opix, Wt);
        }
    }
}

__global__ __launch_bounds__(384, 2)
void aa_fused(const float4* __restrict__ x4, float* __restrict__ out)
{
    extern __shared__ float sm[];
    int* smg = reinterpret_cast<int*>(sm + 2 * GBUF);   // [2] group-id slots

    const int t = threadIdx.x;           // 0..383

    // normalized 1-D gaussian (sigma = 1.5) as literals -> FFMA-imm
    const float Wt[13] = {
        0.00008922f, 0.00102822f, 0.00759740f, 0.03599436f,
        0.10934121f, 0.21296756f, 0.26596430f, 0.21296756f,
        0.10934121f, 0.03599436f, 0.00759740f, 0.00102822f,
        0.00008922f
    };

    // Zero horizontal padding of BOTH buffers:
    // 2 bufs * 3 planes * 4 rows * 16 pad floats = 384 = blockDim
    {
        int bufi  = t / 192;             // 0..1
        int rem   = t - bufi * 192;      // 0..191
        int plane = rem >> 6;            // 0..2
        int rem2  = rem & 63;
        int row   = rem2 >> 4;           // 0..3
        int o     = rem2 & 15;           // 0..15
        sm[bufi * GBUF + plane * GPLANE + row * PROW + (o < 8 ? o : 512 + o)] = 0.f;
    }

    // Planar scatter bases (within one group buffer)
    int sbase[4];
    #pragma unroll
    for (int m = 0; m < 4; ++m) {
        int f    = 4 * t + m;
        int col  = f / 3;
        int chan = f - 3 * col;
        sbase[m] = chan * GPLANE + 8 + col;
    }

    const int j = t & 127;               // output column
    const int c = t >> 7;                // channel plane

    // fetch first group id
    if (t == 0) smg[0] = atomicAdd(&g_counter, 1);
    __syncthreads();

    float* prev_opix = nullptr;
    int q = 0;                           // per-CTA iteration count (uniform)

    while (true) {
        const int g = smg[q & 1];        // group id for this iteration (uniform)
        if (g >= NGRP) break;

        // prefetch next group id into the OTHER slot (no race: different slot;
        // the end-of-iteration barrier publishes it for the next read)
        if (t == 0) smg[(q + 1) & 1] = atomicAdd(&g_counter, 1);

        const int n   = g >> 5;          // image (32 groups per image)
        const int i0g = (g & 31) * 4;    // first output row within image

        const float4* xcol = x4 + (size_t)n * (512 * ROWF4) + t;
        float* opix = out + ((size_t)(n * 128 + i0g) * 128 + j) * 3 + c;

        float*       cur  = sm + (q & 1) * GBUF;
        const float* prev = (q > 0) ? sm + ((q - 1) & 1) * GBUF : nullptr;

        phase1_group(xcol, 4 * i0g - 6, cur, sbase, Wt,
                     prev, j, c, prev_opix);
        __syncthreads();                 // publishes cur buffer + next group id

        prev_opix = opix;
        ++q;
    }

    // last group's horizontal pass (residual tail)
    if (q > 0) {
        const float* last = sm + ((q - 1) & 1) * GBUF;
        #pragma unroll
        for (int rr = 0; rr < GROWS; ++rr)
            phase2_row(last, rr, j, c, prev_opix, Wt);
    }
}

extern "C" void kernel_launch(void* const* d_in, const int* in_sizes, int n_in,
                              void* d_out, int out_size)
{
    (void)in_sizes; (void)n_in; (void)out_size;
    const float4* x4  = (const float4*)d_in[0];
    float*        out = (float*)d_out;

    cudaFuncSetAttribute(aa_fused, cudaFuncAttributeMaxDynamicSharedMemorySize, SMEM_BYTES);

    // reset the work counter each launch (async memset: graph-capturable,
    // allocation-free, keeps kernel_launch deterministic)
    void* ctr = nullptr;
    cudaGetSymbolAddress(&ctr, g_counter);
    cudaMemsetAsync(ctr, 0, sizeof(int));

    aa_fused<<<NCTA, 384, SMEM_BYTES>>>(x4, out);   // 296 = 2/SM x 148 SMs
}

// round 16
// speedup vs baseline: 1.0618x; 1.0618x over previous
#include <cuda_runtime.h>
#include <cuda_bf16.h>

// x: [32, 512, 512, 3] f32  -> out: [32, 128, 128, 3] f32
// 13-tap separable gaussian (sigma=1.5), zero padding, out = blur[4i, 4j]
//
// FINAL (best-measured configuration, R14):
// EXACT-FILL GRID: 296 CTAs (= 2/SM x 148 SMs, zero idle slots).
// Work = 1024 self-contained 4-row groups (32 images x 32 groups);
// CTAs 0..135 process 4 consecutive groups, CTAs 136..295 process 3
// (136*4 + 160*3 = 1024). Under classic bid%148 placement, bids b and
// b+148 co-reside -> 136 SMs carry 7 groups, 12 SMs carry 6 (1.2% imbalance).
// Per group: vertical scatter-accumulate stream (PF=6 LDG.128 ring,
// cache-policy segregation: __ldcs for read-once interior rows, __ldg for
// re-read boundary rows), planar smem staging, horizontal 13-tap pass
// instruction-interleaved into the next group's vertical loop (keeps DRAM
// request issue continuous through the former phase-2 bubble).
// Outputs via __stcs (never re-read).

#define ROWF4   384              // float4 per input image row (512*3/4)
#define PROW    528              // floats per padded plane row (8 + 512 + 8)
#define GROWS   4                // output rows per group
#define GPLANE  (GROWS * PROW)   // floats per plane per group    = 2112
#define GBUF    (3 * GPLANE)     // floats per group buffer       = 6336
#define SMEM_BYTES (2 * GBUF * 4)   // 50688 B (ping-pong)

#define GNIN    (4 * GROWS + 9)  // input rows per group          = 25
#define PF      6                // ring depth; PF>=6 -> R0+s+PF >= 0 always

#define NCTA    296
#define NB4     136              // CTAs carrying 4 groups (rest carry 3)

__device__ __forceinline__ float4 f4zero() { return make_float4(0.f, 0.f, 0.f, 0.f); }

// one horizontal output row rr from a group buffer
__device__ __forceinline__ void phase2_row(
    const float* __restrict__ smbuf, int rr, int j, int c,
    float* __restrict__ opix, const float* __restrict__ Wt)
{
    const float4* sp4 = reinterpret_cast<const float4*>(smbuf)
                      + c * (GPLANE / 4) + rr * (PROW / 4) + j;
    float4 a = sp4[0];
    float4 b = sp4[1];
    float4 d = sp4[2];
    float4 e = sp4[3];
    // s[0..15] = cols 4j-8 .. 4j+7 ; taps at s[2..14]
    float acch;
    acch = Wt[0] * a.z;
    acch = fmaf(Wt[1],  a.w, acch);
    acch = fmaf(Wt[2],  b.x, acch);
    acch = fmaf(Wt[3],  b.y, acch);
    acch = fmaf(Wt[4],  b.z, acch);
    acch = fmaf(Wt[5],  b.w, acch);
    acch = fmaf(Wt[6],  d.x, acch);
    acch = fmaf(Wt[7],  d.y, acch);
    acch = fmaf(Wt[8],  d.z, acch);
    acch = fmaf(Wt[9],  d.w, acch);
    acch = fmaf(Wt[10], e.x, acch);
    acch = fmaf(Wt[11], e.y, acch);
    acch = fmaf(Wt[12], e.z, acch);
    __stcs(&opix[rr * 384], acch);           // streaming store (never re-read)
}

// vertical streaming pass for one 4-row group; if P2BUF != nullptr, one
// phase-2 row of the OTHER buffer is interleaved at s = 5, 11, 17, 23.
__device__ __forceinline__ void phase1_group(
    const float4* __restrict__ xcol, int R0,
    float* __restrict__ smbuf, const int* __restrict__ sbase,
    const float* __restrict__ Wt,
    const float* __restrict__ P2BUF, int j, int c, float* __restrict__ p2opix)
{
    float4 buf[PF];
    #pragma unroll
    for (int s = 0; s < PF; ++s) {               // preload rows R0 .. R0+5
        int r = R0 + s;                          // boundary rows: allocate in L2
        buf[s] = (r >= 0) ? __ldg(xcol + r * ROWF4) : f4zero();
    }

    float4 acc[GROWS];
    #pragma unroll
    for (int q = 0; q < GROWS; ++q) acc[q] = f4zero();

    #pragma unroll
    for (int s = 0; s < GNIN; ++s) {
        const float4 v = buf[s % PF];

        if (s + PF < GNIN) {                     // refill; R0+s+PF >= 0 (PF>=6)
            const int sr = s + PF;               // row index within group: 6..24
            int r = R0 + sr;
            if (r < 512) {
                if (sr >= GNIN - 9) {
                    buf[s % PF] = __ldg(xcol + r * ROWF4);   // re-read: allocate
                } else {
                    buf[s % PF] = __ldcs(xcol + r * ROWF4);  // read-once: evict-first
                }
            } else {
                buf[s % PF] = f4zero();
            }
        }

        const int p = s & 3;
        #pragma unroll
        for (int k = p; k <= 12; k += 4) {       // taps congruent to s mod 4
            const int ii = (s - k) >> 2;
            if (ii >= 0 && ii < GROWS) {
                const float wk = Wt[k];
                acc[ii].x = fmaf(wk, v.x, acc[ii].x);
                acc[ii].y = fmaf(wk, v.y, acc[ii].y);
                acc[ii].z = fmaf(wk, v.z, acc[ii].z);
                acc[ii].w = fmaf(wk, v.w, acc[ii].w);
            }
        }

        // output row ii completes at s = 4*ii + 12 -> flush (4x STS.32)
        if (s >= 12 && ((s - 12) & 3) == 0) {
            const int ii = (s - 12) >> 2;
            const int ro = ii * PROW;
            smbuf[sbase[0] + ro] = acc[ii].x;
            smbuf[sbase[1] + ro] = acc[ii].y;
            smbuf[sbase[2] + ro] = acc[ii].z;
            smbuf[sbase[3] + ro] = acc[ii].w;
        }

        // interleaved horizontal row of the previous group's buffer
        if (P2BUF != nullptr && (s == 5 || s == 11 || s == 17 || s == 23)) {
            phase2_row(P2BUF, (s - 5) / 6, j, c, p2opix, Wt);
        }
    }
}

__global__ __launch_bounds__(384, 2)
void aa_fused(const float4* __restrict__ x4, float* __restrict__ out)
{
    extern __shared__ float sm[];

    const int t = threadIdx.x;           // 0..383
    const int b = blockIdx.x;            // 0..295

    // group range for this CTA: 4 groups for b < NB4, else 3
    const int gstart = (b < NB4) ? 4 * b : 4 * NB4 + 3 * (b - NB4);
    const int gcnt   = (b < NB4) ? 4 : 3;

    // normalized 1-D gaussian (sigma = 1.5) as literals -> FFMA-imm
    const float Wt[13] = {
        0.00008922f, 0.00102822f, 0.00759740f, 0.03599436f,
        0.10934121f, 0.21296756f, 0.26596430f, 0.21296756f,
        0.10934121f, 0.03599436f, 0.00759740f, 0.00102822f,
        0.00008922f
    };

    // Zero horizontal padding of BOTH buffers:
    // 2 bufs * 3 planes * 4 rows * 16 pad floats = 384 = blockDim
    {
        int bufi  = t / 192;             // 0..1
        int rem   = t - bufi * 192;      // 0..191
        int plane = rem >> 6;            // 0..2
        int rem2  = rem & 63;
        int row   = rem2 >> 4;           // 0..3
        int o     = rem2 & 15;           // 0..15
        sm[bufi * GBUF + plane * GPLANE + row * PROW + (o < 8 ? o : 512 + o)] = 0.f;
    }

    // Planar scatter bases (within one group buffer)
    int sbase[4];
    #pragma unroll
    for (int m = 0; m < 4; ++m) {
        int f    = 4 * t + m;
        int col  = f / 3;
        int chan = f - 3 * col;
        sbase[m] = chan * GPLANE + 8 + col;
    }

    const int j = t & 127;               // output column
    const int c = t >> 7;                // channel plane

    float* prev_opix = nullptr;          // output base of previous group

    #pragma unroll 1
    for (int q = 0; q < gcnt; ++q) {
        const int g   = gstart + q;      // global group id
        const int n   = g >> 5;          // image (32 groups per image)
        const int i0g = (g & 31) * 4;    // first output row within image

        const float4* xcol = x4 + (size_t)n * (512 * ROWF4) + t;
        float* opix = out + ((size_t)(n * 128 + i0g) * 128 + j) * 3 + c;

        float*       cur  = sm + (q & 1) * GBUF;
        const float* prev = (q > 0) ? sm + ((q - 1) & 1) * GBUF : nullptr;

        phase1_group(xcol, 4 * i0g - 6, cur, sbase, Wt,
                     prev, j, c, prev_opix);
        __syncthreads();

        prev_opix = opix;
    }

    // last group's horizontal pass (residual tail)
    {
        const float* last = sm + ((gcnt - 1) & 1) * GBUF;
        #pragma unroll
        for (int rr = 0; rr < GROWS; ++rr)
            phase2_row(last, rr, j, c, prev_opix, Wt);
    }
}

extern "C" void kernel_launch(void* const* d_in, const int* in_sizes, int n_in,
                              void* d_out, int out_size)
{
    (void)in_sizes; (void)n_in; (void)out_size;
    const float4* x4  = (const float4*)d_in[0];
    float*        out = (float*)d_out;

    cudaFuncSetAttribute(aa_fused, cudaFuncAttributeMaxDynamicSharedMemorySize, SMEM_BYTES);

    aa_fused<<<NCTA, 384, SMEM_BYTES>>>(x4, out);   // 296 = 2/SM x 148, exact fill
}